// round 14
// baseline (speedup 1.0000x reference)
#include <cuda_runtime.h>
#include <math.h>

#define B_   2
#define S_   2048
#define D_   1024
#define H_   16
#define HD_  64
#define M_TOT (B_ * S_)   // 4096

typedef unsigned long long u64;

// packed f32x2 helpers (sm_100+ PTX; FFMA2 is unreachable from plain C++)
#define FFMA2(d, a, b, c) asm("fma.rn.f32x2 %0, %1, %2, %3;" : "=l"(d) : "l"(a), "l"(b), "l"(c))
#define FMUL2(d, a, b)    asm("mul.rn.f32x2 %0, %1, %2;"     : "=l"(d) : "l"(a), "l"(b))
#define BCAST2(d, a)      asm("mov.b64 %0, {%1, %1};"        : "=l"(d) : "f"(a))
#define UNPACK2(lo, hi, s) asm("mov.b64 {%0, %1}, %2;" : "=f"(lo), "=f"(hi) : "l"(s))

// ---------------- scratch (no allocs allowed) ----------------
__device__ float g_q[(size_t)B_ * H_ * S_ * HD_];     // [B,H,S,HD]
__device__ float g_k[(size_t)B_ * H_ * S_ * HD_];
__device__ float g_v[(size_t)B_ * H_ * S_ * HD_];
__device__ float g_attn[(size_t)B_ * S_ * D_];        // [B,S,D]

// ==================== GEMM tiling ====================
#define BM 128
#define BN 128
#define BK 8
#define TM 8
#define TN 8

// ---------------- fused QKV projection ----------------
__global__ __launch_bounds__(256, 2) void qkv_gemm(
    const float* __restrict__ xq, const float* __restrict__ xk, const float* __restrict__ xv,
    const float* __restrict__ wq, const float* __restrict__ bq,
    const float* __restrict__ wk, const float* __restrict__ bk,
    const float* __restrict__ wv, const float* __restrict__ bv)
{
    const float* X; const float* W; const float* bias; float* out;
    if (blockIdx.z == 0)      { X = xq; W = wq; bias = bq; out = g_q; }
    else if (blockIdx.z == 1) { X = xk; W = wk; bias = bk; out = g_k; }
    else                      { X = xv; W = wv; bias = bv; out = g_v; }

    __shared__ float As[BK][BM];
    __shared__ float Bs[BK][BN];

    const int n0 = blockIdx.x * BN;
    const int m0 = blockIdx.y * BM;
    const int tid = threadIdx.x;
    const int tx = tid & 15;
    const int ty = tid >> 4;

    const int arow = tid >> 1;
    const int acol = (tid & 1) * 4;
    const int brow = tid >> 5;
    const int bcol = (tid & 31) * 4;

    const int bh  = (n0 + bcol) >> 6;
    const int bhd = (n0 + bcol) & 63;

    // packed accumulators: acc2[i][jp] = (col 2jp, col 2jp+1) of micro-tile row i
    u64 acc2[TM][TN / 2];
    #pragma unroll
    for (int i = 0; i < TM; i++)
        #pragma unroll
        for (int j = 0; j < TN / 2; j++) acc2[i][j] = 0ull;

    float4 a_pf = *reinterpret_cast<const float4*>(&X[(size_t)(m0 + arow) * D_ + acol]);
    float4 b_pf = *reinterpret_cast<const float4*>(&W[((size_t)bh * D_ + brow) * HD_ + bhd]);

    for (int k0 = 0; k0 < D_; k0 += BK) {
        As[acol + 0][arow] = a_pf.x;
        As[acol + 1][arow] = a_pf.y;
        As[acol + 2][arow] = a_pf.z;
        As[acol + 3][arow] = a_pf.w;
        *reinterpret_cast<float4*>(&Bs[brow][bcol]) = b_pf;
        __syncthreads();

        if (k0 + BK < D_) {
            a_pf = *reinterpret_cast<const float4*>(
                &X[(size_t)(m0 + arow) * D_ + (k0 + BK) + acol]);
            b_pf = *reinterpret_cast<const float4*>(
                &W[((size_t)bh * D_ + (k0 + BK + brow)) * HD_ + bhd]);
        }

        #pragma unroll
        for (int k = 0; k < BK; k++) {
            float a[TM];
            #pragma unroll
            for (int i = 0; i < TM; i += 4) {
                float4 t = *reinterpret_cast<const float4*>(&As[k][ty * TM + i]);
                a[i] = t.x; a[i+1] = t.y; a[i+2] = t.z; a[i+3] = t.w;
            }
            // b as packed pairs straight from smem (16B-aligned)
            ulonglong2 bA = *reinterpret_cast<const ulonglong2*>(&Bs[k][tx * TN]);
            ulonglong2 bB = *reinterpret_cast<const ulonglong2*>(&Bs[k][tx * TN + 4]);
            u64 bp[4] = {bA.x, bA.y, bB.x, bB.y};
            #pragma unroll
            for (int i = 0; i < TM; i++) {
                u64 aa; BCAST2(aa, a[i]);
                #pragma unroll
                for (int j = 0; j < TN / 2; j++)
                    FFMA2(acc2[i][j], aa, bp[j], acc2[i][j]);
            }
        }
        __syncthreads();
    }

    #pragma unroll
    for (int i = 0; i < TM; i++) {
        int m = m0 + ty * TM + i;
        int bidx = m >> 11;
        int s = m & (S_ - 1);
        #pragma unroll
        for (int jp = 0; jp < TN / 2; jp += 2) {
            int n = n0 + tx * TN + jp * 2;
            int h = n >> 6, hd = n & 63;
            float4 bb = *reinterpret_cast<const float4*>(&bias[h * HD_ + hd]);
            float f0, f1, f2, f3;
            UNPACK2(f0, f1, acc2[i][jp]);
            UNPACK2(f2, f3, acc2[i][jp + 1]);
            float4 o;
            o.x = f0 + bb.x; o.y = f1 + bb.y;
            o.z = f2 + bb.z; o.w = f3 + bb.w;
            *reinterpret_cast<float4*>(
                &out[(((size_t)bidx * H_ + h) * S_ + s) * HD_ + hd]) = o;
        }
    }
}

// ---------------- output projection ----------------
__global__ __launch_bounds__(256, 2) void out_gemm(
    const float* __restrict__ Wo, const float* __restrict__ bo, float* __restrict__ Y)
{
    __shared__ float As[BK][BM];
    __shared__ float Bs[BK][BN];

    const int n0 = blockIdx.x * BN;
    const int m0 = blockIdx.y * BM;
    const int tid = threadIdx.x;
    const int tx = tid & 15;
    const int ty = tid >> 4;

    const int arow = tid >> 1;
    const int acol = (tid & 1) * 4;
    const int brow = tid >> 5;
    const int bcol = (tid & 31) * 4;

    u64 acc2[TM][TN / 2];
    #pragma unroll
    for (int i = 0; i < TM; i++)
        #pragma unroll
        for (int j = 0; j < TN / 2; j++) acc2[i][j] = 0ull;

    float4 a_pf = *reinterpret_cast<const float4*>(&g_attn[(size_t)(m0 + arow) * D_ + acol]);
    float4 b_pf = *reinterpret_cast<const float4*>(&Wo[(size_t)brow * D_ + n0 + bcol]);

    for (int k0 = 0; k0 < D_; k0 += BK) {
        As[acol + 0][arow] = a_pf.x;
        As[acol + 1][arow] = a_pf.y;
        As[acol + 2][arow] = a_pf.z;
        As[acol + 3][arow] = a_pf.w;
        *reinterpret_cast<float4*>(&Bs[brow][bcol]) = b_pf;
        __syncthreads();

        if (k0 + BK < D_) {
            a_pf = *reinterpret_cast<const float4*>(
                &g_attn[(size_t)(m0 + arow) * D_ + (k0 + BK) + acol]);
            b_pf = *reinterpret_cast<const float4*>(
                &Wo[(size_t)(k0 + BK + brow) * D_ + n0 + bcol]);
        }

        #pragma unroll
        for (int k = 0; k < BK; k++) {
            float a[TM];
            #pragma unroll
            for (int i = 0; i < TM; i += 4) {
                float4 t = *reinterpret_cast<const float4*>(&As[k][ty * TM + i]);
                a[i] = t.x; a[i+1] = t.y; a[i+2] = t.z; a[i+3] = t.w;
            }
            ulonglong2 bA = *reinterpret_cast<const ulonglong2*>(&Bs[k][tx * TN]);
            ulonglong2 bB = *reinterpret_cast<const ulonglong2*>(&Bs[k][tx * TN + 4]);
            u64 bp[4] = {bA.x, bA.y, bB.x, bB.y};
            #pragma unroll
            for (int i = 0; i < TM; i++) {
                u64 aa; BCAST2(aa, a[i]);
                #pragma unroll
                for (int j = 0; j < TN / 2; j++)
                    FFMA2(acc2[i][j], aa, bp[j], acc2[i][j]);
            }
        }
        __syncthreads();
    }

    #pragma unroll
    for (int i = 0; i < TM; i++) {
        int m = m0 + ty * TM + i;
        #pragma unroll
        for (int jp = 0; jp < TN / 2; jp += 2) {
            int n = n0 + tx * TN + jp * 2;
            float4 bb = *reinterpret_cast<const float4*>(&bo[n]);
            float f0, f1, f2, f3;
            UNPACK2(f0, f1, acc2[i][jp]);
            UNPACK2(f2, f3, acc2[i][jp + 1]);
            float4 o;
            o.x = f0 + bb.x; o.y = f1 + bb.y;
            o.z = f2 + bb.z; o.w = f3 + bb.w;
            *reinterpret_cast<float4*>(&Y[(size_t)m * D_ + n]) = o;
        }
    }
}

// ---------------- causal flash attention (packed f32x2 GEMMs) ----------------
#define AT_BM 64
#define AT_BN 32
#define PS_STRIDE 68

__global__ __launch_bounds__(128) void attn_kernel()
{
    __shared__ float Qs [HD_][AT_BM];        // [d][row], pre-scaled
    __shared__ float Kst[HD_][AT_BN];        // [d][key]
    __shared__ float Vs [AT_BN][HD_];        // [key][d]
    __shared__ float Ps [AT_BN][PS_STRIDE];  // [key][row]

    const int nqb = S_ / AT_BM;
    const int qb = (nqb - 1) - blockIdx.x;   // heavy causal blocks first
    const int h  = blockIdx.y;
    const int b  = blockIdx.z;
    const int tid = threadIdx.x;
    const int tx = tid & 7;
    const int ty = tid >> 3;
    const int qg0 = qb * AT_BM;

    const float qscale = 0.125f * 1.4426950408889634f;  // 1/sqrt(HD) * log2(e)

    const float* qbase = &g_q[(((size_t)b * H_ + h) * S_ + qg0) * HD_];
    const float* kbase = &g_k[(((size_t)b * H_ + h) * S_) * HD_];
    const float* vbase = &g_v[(((size_t)b * H_ + h) * S_) * HD_];

    {
        int row = tid & 63;
        int c0  = (tid >> 6) * 32;
        #pragma unroll
        for (int i = 0; i < 32; i += 4) {
            float4 t = *reinterpret_cast<const float4*>(&qbase[(size_t)row * HD_ + c0 + i]);
            Qs[c0 + i + 0][row] = t.x * qscale;
            Qs[c0 + i + 1][row] = t.y * qscale;
            Qs[c0 + i + 2][row] = t.z * qscale;
            Qs[c0 + i + 3][row] = t.w * qscale;
        }
    }

    // packed output accumulators: acc2[r][jp] = dims (tx*8+2jp, +1)
    u64 acc2[4][4];
    #pragma unroll
    for (int r = 0; r < 4; r++)
        #pragma unroll
        for (int j = 0; j < 4; j++) acc2[r][j] = 0ull;
    float m_i[4] = {-INFINITY, -INFINITY, -INFINITY, -INFINITY};
    float l_i[4] = {0.f, 0.f, 0.f, 0.f};

    const int ntiles = 2 * (qb + 1);
    for (int t = 0; t < ntiles; t++) {
        const int kb = t * AT_BN;
        __syncthreads();

        {
            int key = tid & 31;
            int c0  = (tid >> 5) * 16;
            #pragma unroll
            for (int i = 0; i < 16; i += 4) {
                float4 tt = *reinterpret_cast<const float4*>(
                    &kbase[(size_t)(kb + key) * HD_ + c0 + i]);
                Kst[c0 + i + 0][key] = tt.x;
                Kst[c0 + i + 1][key] = tt.y;
                Kst[c0 + i + 2][key] = tt.z;
                Kst[c0 + i + 3][key] = tt.w;
            }
        }
        #pragma unroll
        for (int i = 0; i < 4; i++) {
            int idx = tid + i * 128;
            int r = idx >> 4;
            int c = (idx & 15) * 4;
            *reinterpret_cast<float4*>(&Vs[r][c]) =
                *reinterpret_cast<const float4*>(&vbase[(size_t)(kb + r) * HD_ + c]);
        }
        __syncthreads();

        // ---- GEMM1 (packed): s2[r][cp] over 64 dims ----
        u64 s2[4][2];
        #pragma unroll
        for (int r = 0; r < 4; r++) { s2[r][0] = 0ull; s2[r][1] = 0ull; }

        #pragma unroll 8
        for (int k = 0; k < HD_; k++) {
            float4 a = *reinterpret_cast<const float4*>(&Qs[k][ty * 4]);
            ulonglong2 bp = *reinterpret_cast<const ulonglong2*>(&Kst[k][tx * 4]);
            float av[4] = {a.x, a.y, a.z, a.w};
            #pragma unroll
            for (int r = 0; r < 4; r++) {
                u64 aa; BCAST2(aa, av[r]);
                FFMA2(s2[r][0], aa, bp.x, s2[r][0]);
                FFMA2(s2[r][1], aa, bp.y, s2[r][1]);
            }
        }

        float s[4][4];
        #pragma unroll
        for (int r = 0; r < 4; r++) {
            UNPACK2(s[r][0], s[r][1], s2[r][0]);
            UNPACK2(s[r][2], s[r][3], s2[r][1]);
        }

        if (kb + AT_BN - 1 > qg0) {
            #pragma unroll
            for (int r = 0; r < 4; r++)
                #pragma unroll
                for (int c = 0; c < 4; c++)
                    if (kb + tx * 4 + c > qg0 + ty * 4 + r) s[r][c] = -INFINITY;
        }

        // ---- online softmax (log2 domain) ----
        #pragma unroll
        for (int r = 0; r < 4; r++) {
            float mt = fmaxf(fmaxf(s[r][0], s[r][1]), fmaxf(s[r][2], s[r][3]));
            mt = fmaxf(mt, __shfl_xor_sync(0xffffffffu, mt, 1));
            mt = fmaxf(mt, __shfl_xor_sync(0xffffffffu, mt, 2));
            mt = fmaxf(mt, __shfl_xor_sync(0xffffffffu, mt, 4));
            float mnew = fmaxf(m_i[r], mt);
            float corr = exp2f(m_i[r] - mnew);
            float p0 = exp2f(s[r][0] - mnew);
            float p1 = exp2f(s[r][1] - mnew);
            float p2 = exp2f(s[r][2] - mnew);
            float p3 = exp2f(s[r][3] - mnew);
            s[r][0] = p0; s[r][1] = p1; s[r][2] = p2; s[r][3] = p3;
            float rs = (p0 + p1) + (p2 + p3);
            rs += __shfl_xor_sync(0xffffffffu, rs, 1);
            rs += __shfl_xor_sync(0xffffffffu, rs, 2);
            rs += __shfl_xor_sync(0xffffffffu, rs, 4);
            l_i[r] = l_i[r] * corr + rs;
            u64 cc; BCAST2(cc, corr);
            #pragma unroll
            for (int j = 0; j < 4; j++) FMUL2(acc2[r][j], acc2[r][j], cc);
            m_i[r] = mnew;
        }

        #pragma unroll
        for (int c = 0; c < 4; c++)
            #pragma unroll
            for (int r = 0; r < 4; r++)
                Ps[tx * 4 + c][ty * 4 + r] = s[r][c];
        __syncthreads();

        // ---- GEMM2 (packed): acc2 += P x V over 32 keys ----
        #pragma unroll 4
        for (int k = 0; k < AT_BN; k++) {
            float4 a = *reinterpret_cast<const float4*>(&Ps[k][ty * 4]);
            ulonglong2 vA = *reinterpret_cast<const ulonglong2*>(&Vs[k][tx * 8]);
            ulonglong2 vB = *reinterpret_cast<const ulonglong2*>(&Vs[k][tx * 8 + 4]);
            u64 vp[4] = {vA.x, vA.y, vB.x, vB.y};
            float av[4] = {a.x, a.y, a.z, a.w};
            #pragma unroll
            for (int r = 0; r < 4; r++) {
                u64 aa; BCAST2(aa, av[r]);
                #pragma unroll
                for (int j = 0; j < 4; j++)
                    FFMA2(acc2[r][j], aa, vp[j], acc2[r][j]);
            }
        }
    }

    // ---- epilogue ----
    #pragma unroll
    for (int r = 0; r < 4; r++) {
        float inv = 1.f / l_i[r];
        int row = qg0 + ty * 4 + r;
        float* optr = &g_attn[((size_t)b * S_ + row) * D_ + h * HD_ + tx * 8];
        float f[8];
        UNPACK2(f[0], f[1], acc2[r][0]);
        UNPACK2(f[2], f[3], acc2[r][1]);
        UNPACK2(f[4], f[5], acc2[r][2]);
        UNPACK2(f[6], f[7], acc2[r][3]);
        float4 o0, o1;
        o0.x = f[0] * inv; o0.y = f[1] * inv; o0.z = f[2] * inv; o0.w = f[3] * inv;
        o1.x = f[4] * inv; o1.y = f[5] * inv; o1.z = f[6] * inv; o1.w = f[7] * inv;
        *reinterpret_cast<float4*>(optr)     = o0;
        *reinterpret_cast<float4*>(optr + 4) = o1;
    }
}

// ---------------- launch ----------------
extern "C" void kernel_launch(void* const* d_in, const int* in_sizes, int n_in,
                              void* d_out, int out_size)
{
    const float* xq = (const float*)d_in[0];
    const float* xk = (const float*)d_in[1];
    const float* xv = (const float*)d_in[2];
    // d_in[3] is the (ignored) mask
    const float* Wq = (const float*)d_in[4];
    const float* bq = (const float*)d_in[5];
    const float* Wk = (const float*)d_in[6];
    const float* bk = (const float*)d_in[7];
    const float* Wv = (const float*)d_in[8];
    const float* bv = (const float*)d_in[9];
    const float* Wo = (const float*)d_in[10];
    const float* bo = (const float*)d_in[11];
    float* out = (float*)d_out;

    dim3 g1(D_ / BN, M_TOT / BM, 3);
    qkv_gemm<<<g1, 256>>>(xq, xk, xv, Wq, bq, Wk, bk, Wv, bv);

    dim3 g2(S_ / AT_BM, H_, B_);
    attn_kernel<<<g2, 128>>>();

    dim3 g3(D_ / BN, M_TOT / BM);
    out_gemm<<<g3, 256>>>(Wo, bo, out);
}